// round 9
// baseline (speedup 1.0000x reference)
#include <cuda_runtime.h>
#include <cuda_bf16.h>
#include <mma.h>
#include <float.h>
#include <cstdint>
using namespace nvcuda;

#define N_NODES 100000
#define N_EDGES 1000000
#define F_IN    128
#define F_HID   256
#define F_OUT   40
#define SCAN_B  98

// ---------------- scratch ----------------------------------------------------
__device__ int   g_cnt   [N_NODES];
__device__ float g_dinv  [N_NODES];
__device__ int   g_srcA  [N_EDGES];
__device__ int   g_dstA  [N_EDGES];
__device__ int   g_rowptr[N_NODES + 1];
__device__ int   g_cursor[N_NODES];
__device__ int   g_csr_src[N_EDGES];
__device__ float g_csr_w  [N_EDGES];
__device__ int   g_bsum[SCAN_B];
__device__ int   g_boff[SCAN_B];
__device__ __align__(16) float g_h2 [(size_t)N_NODES * F_OUT];
__device__ __align__(16) __nv_bfloat16 g_w1h[128 * 256];   // [k][n] row-major
__device__ __align__(16) __nv_bfloat16 g_w1l[128 * 256];
__device__ __align__(16) __nv_bfloat16 g_w2h[256 * 48];    // [k][n48], n>=40 zero
__device__ __align__(16) __nv_bfloat16 g_w2l[256 * 48];
__device__ int   g_is32 = 0;   // sticky: dtype is fixed across replays

__device__ __forceinline__ void bsplit(float a, __nv_bfloat16& hi, __nv_bfloat16& lo) {
    hi = __float2bfloat16_rn(a);
    lo = __float2bfloat16_rn(a - __bfloat162float(hi));
}
__device__ __forceinline__ uint32_t pack_bf2(__nv_bfloat16 a, __nv_bfloat16 b) {
    __nv_bfloat162 t(a, b);
    return *(uint32_t*)&t;
}

// ---------------- fused: zero counts + dtype probe ----------------------------
__global__ void k_pre(const long long* __restrict__ e64) {
    int i = blockIdx.x * blockDim.x + threadIdx.x;
    if (i < N_NODES) g_cnt[i] = 0;
    if (blockIdx.x == 0) {
        for (int t = threadIdx.x; t < 8192; t += 256) {
            long long v = e64[(long long)t * 122];
            if (v < 0 || v >= N_NODES) g_is32 = 1;   // sticky across replays
        }
    }
}

__global__ void k_edges(const void* __restrict__ edge) {
    int e = blockIdx.x * blockDim.x + threadIdx.x;
    if (e >= N_EDGES) return;
    int s, d;
    if (g_is32) {
        const int* e32 = (const int*)edge;
        s = e32[e];  d = e32[N_EDGES + e];
    } else {
        const long long* e64 = (const long long*)edge;
        s = (int)e64[e];  d = (int)e64[N_EDGES + e];
    }
    g_srcA[e] = s;
    g_dstA[e] = d;
    atomicAdd(&g_cnt[d], 1);
}

// scan stage 1 (+ fused dinv)
__global__ __launch_bounds__(1024) void k_scan1() {
    __shared__ int wsum[32];
    int tid = threadIdx.x, lane = tid & 31, w = tid >> 5;
    int i = blockIdx.x * 1024 + tid;
    int v = 0;
    if (i < N_NODES) {
        v = g_cnt[i];
        g_dinv[i] = rsqrtf((float)(v + 1));
    }
    int r = v;
    #pragma unroll
    for (int o = 16; o; o >>= 1) r += __shfl_xor_sync(0xffffffffu, r, o);
    if (lane == 0) wsum[w] = r;
    __syncthreads();
    if (w == 0) {
        int y = wsum[lane];
        #pragma unroll
        for (int o = 16; o; o >>= 1) y += __shfl_xor_sync(0xffffffffu, y, o);
        if (lane == 0) g_bsum[blockIdx.x] = y;
    }
}

// parallel scan of the 98 block sums (1 block, 128 threads)
__global__ void k_scan2() {
    __shared__ int wsum[4];
    int tid = threadIdx.x, lane = tid & 31, w = tid >> 5;
    int v = (tid < SCAN_B) ? g_bsum[tid] : 0;
    int x = v;
    #pragma unroll
    for (int o = 1; o < 32; o <<= 1) {
        int y = __shfl_up_sync(0xffffffffu, x, o);
        if (lane >= o) x += y;
    }
    if (lane == 31) wsum[w] = x;
    __syncthreads();
    int base = 0;
    #pragma unroll
    for (int b = 0; b < 4; b++) base += (b < w) ? wsum[b] : 0;
    int incl = base + x;
    if (tid < SCAN_B) g_boff[tid] = incl - v;
    if (tid == SCAN_B - 1) g_rowptr[N_NODES] = incl;
}

__global__ __launch_bounds__(1024) void k_scan3() {
    __shared__ int wsum[32];
    int tid = threadIdx.x, lane = tid & 31, w = tid >> 5;
    int i = blockIdx.x * 1024 + tid;
    int v = (i < N_NODES) ? g_cnt[i] : 0;
    int x = v;
    #pragma unroll
    for (int o = 1; o < 32; o <<= 1) {
        int y = __shfl_up_sync(0xffffffffu, x, o);
        if (lane >= o) x += y;
    }
    if (lane == 31) wsum[w] = x;
    __syncthreads();
    if (w == 0) {
        int y = wsum[lane];
        #pragma unroll
        for (int o = 1; o < 32; o <<= 1) {
            int z = __shfl_up_sync(0xffffffffu, y, o);
            if (lane >= o) y += z;
        }
        wsum[lane] = y;
    }
    __syncthreads();
    if (i < N_NODES) {
        int off = g_boff[blockIdx.x] + x - v + (w > 0 ? wsum[w - 1] : 0);
        g_rowptr[i] = off;
        g_cursor[i] = off;
    }
}
__global__ void k_place() {
    int e = blockIdx.x * blockDim.x + threadIdx.x;
    if (e >= N_EDGES) return;
    int s = g_srcA[e], d = g_dstA[e];
    int pos = atomicAdd(&g_cursor[d], 1);
    g_csr_src[pos] = s;
    g_csr_w[pos]   = g_dinv[s] * g_dinv[d];
}

// ---------------- weight prep: bf16 split ------------------------------------
__global__ void k_prep_w1(const float* __restrict__ W1) {
    int i = blockIdx.x * blockDim.x + threadIdx.x;   // i = k*256 + n
    if (i >= F_IN * F_HID) return;
    __nv_bfloat16 h, l;
    bsplit(W1[i], h, l);
    g_w1h[i] = h;
    g_w1l[i] = l;
}
__global__ void k_prep_w2(const float* __restrict__ W2) {
    int i = blockIdx.x * blockDim.x + threadIdx.x;   // i = k*48 + n
    if (i >= 48 * F_HID) return;
    int k = i / 48, n = i - k * 48;
    float v = (n < F_OUT) ? W2[(size_t)k * F_OUT + n] : 0.f;
    __nv_bfloat16 h, l;
    bsplit(v, h, l);
    g_w2h[i] = h;
    g_w2l[i] = l;
}

// ---------------- fused GCN layer-1+MLP: h2 = relu((A_norm x)@W1+b1) @ W2 ----
// 64 rows/block, 256 threads (8 warps). Gather (CSR) -> smem bf16 hi/lo,
// then split-bf16 (3 MMAs) GEMM1 and GEMM2. Smem aliasing for 2 CTAs/SM.
#define SM_H    0
#define SM_A    67584
#define MLP_SMEM 102400

__device__ __forceinline__ void stage_b1(char* sm, int buf, int k, int tid) {
    __nv_bfloat16* Bh = (__nv_bfloat16*)(sm + SM_H + buf * 16896);
    __nv_bfloat16* Bl = (__nv_bfloat16*)(sm + SM_H + buf * 16896 + 8448);
    #pragma unroll
    for (int u = tid; u < 512; u += 256) {
        int r = u >> 5, c8 = (u & 31) << 3;
        *(uint4*)&Bh[r * 264 + c8] = *(const uint4*)&g_w1h[(k * 16 + r) * 256 + c8];
        *(uint4*)&Bl[r * 264 + c8] = *(const uint4*)&g_w1l[(k * 16 + r) * 256 + c8];
    }
}

__global__ __launch_bounds__(256, 2) void k_mlp(const float* __restrict__ x,
                                                const float* __restrict__ b1) {
    extern __shared__ char sm[];
    __nv_bfloat16* Hh = (__nv_bfloat16*)(sm + SM_H);
    __nv_bfloat16* Hl = (__nv_bfloat16*)(sm + SM_H + 33792);
    __nv_bfloat16* Ah = (__nv_bfloat16*)(sm + SM_A);
    __nv_bfloat16* Al = (__nv_bfloat16*)(sm + SM_A + 17408);
    float*         stg = (float*)(sm + SM_A);      // aliases A (dead in epilogues)

    int tid = threadIdx.x, wid = tid >> 5, lane = tid & 31;
    int bm = blockIdx.x * 64;
    int rg = wid >> 1, cg = wid & 1;     // 4 row-groups x 2 col-groups

    // ---- gather: aggregate this block's 64 rows straight from x (CSR) ----
    const float4* x4 = (const float4*)x;
    #pragma unroll
    for (int rr = 0; rr < 8; rr++) {
        int r = wid * 8 + rr;
        int d = bm + r;
        float4 acc = make_float4(0.f, 0.f, 0.f, 0.f);
        if (d < N_NODES) {
            float dv = g_dinv[d];
            float d2 = dv * dv;
            float4 v = x4[(size_t)d * 32 + lane];
            acc = make_float4(v.x * d2, v.y * d2, v.z * d2, v.w * d2);
            int p0 = g_rowptr[d], p1 = g_rowptr[d + 1];
            int p = p0;
            for (; p + 3 < p1; p += 4) {
                int   s0 = g_csr_src[p],     s1 = g_csr_src[p + 1];
                int   s2 = g_csr_src[p + 2], s3 = g_csr_src[p + 3];
                float w0 = g_csr_w[p],       w1 = g_csr_w[p + 1];
                float w2 = g_csr_w[p + 2],   w3 = g_csr_w[p + 3];
                float4 u0 = x4[(size_t)s0 * 32 + lane];
                float4 u1 = x4[(size_t)s1 * 32 + lane];
                float4 u2 = x4[(size_t)s2 * 32 + lane];
                float4 u3 = x4[(size_t)s3 * 32 + lane];
                acc.x += w0 * u0.x + w1 * u1.x + w2 * u2.x + w3 * u3.x;
                acc.y += w0 * u0.y + w1 * u1.y + w2 * u2.y + w3 * u3.y;
                acc.z += w0 * u0.z + w1 * u1.z + w2 * u2.z + w3 * u3.z;
                acc.w += w0 * u0.w + w1 * u1.w + w2 * u2.w + w3 * u3.w;
            }
            for (; p < p1; p++) {
                int   s = g_csr_src[p];
                float w = g_csr_w[p];
                float4 u = x4[(size_t)s * 32 + lane];
                acc.x += w * u.x; acc.y += w * u.y;
                acc.z += w * u.z; acc.w += w * u.w;
            }
        }
        __nv_bfloat16 h0, l0, h1, l1, h2, l2, h3, l3;
        bsplit(acc.x, h0, l0); bsplit(acc.y, h1, l1);
        bsplit(acc.z, h2, l2); bsplit(acc.w, h3, l3);
        uint32_t hp0 = pack_bf2(h0, h1), hp1 = pack_bf2(h2, h3);
        uint32_t lp0 = pack_bf2(l0, l1), lp1 = pack_bf2(l2, l3);
        *(uint32_t*)&Ah[r * 136 + lane * 4]     = hp0;
        *(uint32_t*)&Ah[r * 136 + lane * 4 + 2] = hp1;
        *(uint32_t*)&Al[r * 136 + lane * 4]     = lp0;
        *(uint32_t*)&Al[r * 136 + lane * 4 + 2] = lp1;
    }
    stage_b1(sm, 0, 0, tid);
    __syncthreads();

    // ---- phase A: H = relu(A @ W1 + b1), B1 double-buffered ----
    wmma::fragment<wmma::accumulator, 16, 16, 16, float> acc[8];
    #pragma unroll
    for (int j = 0; j < 8; j++) wmma::fill_fragment(acc[j], 0.f);

    #pragma unroll
    for (int k = 0; k < 8; k++) {
        int cur = k & 1;
        if (k < 7) stage_b1(sm, 1 - cur, k + 1, tid);
        __nv_bfloat16* B1h = (__nv_bfloat16*)(sm + SM_H + cur * 16896);
        __nv_bfloat16* B1l = (__nv_bfloat16*)(sm + SM_H + cur * 16896 + 8448);

        wmma::fragment<wmma::matrix_a, 16, 16, 16, __nv_bfloat16, wmma::row_major> ah, al;
        wmma::load_matrix_sync(ah, &Ah[(rg * 16) * 136 + k * 16], 136);
        wmma::load_matrix_sync(al, &Al[(rg * 16) * 136 + k * 16], 136);
        #pragma unroll
        for (int j = 0; j < 8; j++) {
            wmma::fragment<wmma::matrix_b, 16, 16, 16, __nv_bfloat16, wmma::row_major> bh, bl;
            wmma::load_matrix_sync(bh, &B1h[cg * 128 + j * 16], 264);
            wmma::load_matrix_sync(bl, &B1l[cg * 128 + j * 16], 264);
            wmma::mma_sync(acc[j], ah, bh, acc[j]);
            wmma::mma_sync(acc[j], ah, bl, acc[j]);
            wmma::mma_sync(acc[j], al, bh, acc[j]);
        }
        __syncthreads();
    }

    // ---- epilogue A: bias + relu + split -> H smem ----
    #pragma unroll
    for (int j = 0; j < 8; j++) {
        wmma::store_matrix_sync(&stg[wid * 256], acc[j], 16, wmma::mem_row_major);
        __syncwarp();
        int r  = lane >> 1, c0 = (lane & 1) * 8;
        int col = cg * 128 + j * 16 + c0;
        uint32_t hw[4], lw[4];
        #pragma unroll
        for (int e = 0; e < 8; e += 2) {
            float f0 = fmaxf(stg[wid * 256 + r * 16 + c0 + e]     + b1[col + e],     0.f);
            float f1 = fmaxf(stg[wid * 256 + r * 16 + c0 + e + 1] + b1[col + e + 1], 0.f);
            __nv_bfloat16 h0, l0, h1, l1;
            bsplit(f0, h0, l0); bsplit(f1, h1, l1);
            hw[e >> 1] = pack_bf2(h0, h1);
            lw[e >> 1] = pack_bf2(l0, l1);
        }
        int row = rg * 16 + r;
        *(uint4*)&Hh[row * 264 + col] = *(uint4*)hw;
        *(uint4*)&Hl[row * 264 + col] = *(uint4*)lw;
        __syncwarp();
    }
    __syncthreads();

    // ---- phase B: H2 = H @ W2 (N padded to 48: cg0 -> 2 tiles, cg1 -> 1) ----
    int nTiles = (cg == 0) ? 2 : 1;
    wmma::fragment<wmma::accumulator, 16, 16, 16, float> acc2[2];
    #pragma unroll
    for (int j = 0; j < 2; j++) wmma::fill_fragment(acc2[j], 0.f);

    #pragma unroll
    for (int k = 0; k < 16; k++) {
        wmma::fragment<wmma::matrix_a, 16, 16, 16, __nv_bfloat16, wmma::row_major> ah, al;
        wmma::load_matrix_sync(ah, &Hh[(rg * 16) * 264 + k * 16], 264);
        wmma::load_matrix_sync(al, &Hl[(rg * 16) * 264 + k * 16], 264);
        for (int j = 0; j < nTiles; j++) {
            int nc = (cg == 0) ? j * 16 : 32;
            wmma::fragment<wmma::matrix_b, 16, 16, 16, __nv_bfloat16, wmma::row_major> bh, bl;
            wmma::load_matrix_sync(bh, &g_w2h[(k * 16) * 48 + nc], 48);
            wmma::load_matrix_sync(bl, &g_w2l[(k * 16) * 48 + nc], 48);
            wmma::mma_sync(acc2[j], ah, bh, acc2[j]);
            wmma::mma_sync(acc2[j], ah, bl, acc2[j]);
            wmma::mma_sync(acc2[j], al, bh, acc2[j]);
        }
    }

    // ---- epilogue B: write h2 (cols < 40) ----
    for (int j = 0; j < nTiles; j++) {
        int ncb = (cg == 0) ? j * 16 : 32;
        wmma::store_matrix_sync(&stg[wid * 256], acc2[j], 16, wmma::mem_row_major);
        __syncwarp();
        int r  = lane >> 1, c0 = (lane & 1) * 8;
        int row = bm + rg * 16 + r;
        int col = ncb + c0;
        if (row < N_NODES && col < F_OUT) {
            float* dst = g_h2 + (size_t)row * F_OUT + col;
            *(float4*)(dst)     = *(float4*)&stg[wid * 256 + r * 16 + c0];
            *(float4*)(dst + 4) = *(float4*)&stg[wid * 256 + r * 16 + c0 + 4];
        }
        __syncwarp();
    }
}

// ---------------- layer-2 aggregation + bias + log_softmax (fused) -----------
// 2 dst per warp (16-lane halves); lanes q<10 own one float4 each.
__global__ void k_layer2(const float* __restrict__ b2, float* __restrict__ out) {
    int t    = blockIdx.x * blockDim.x + threadIdx.x;
    int warp = t >> 5;
    int lane = t & 31;
    int half = lane >> 4;
    int q    = lane & 15;
    int d    = warp * 2 + half;
    const float4* h4 = (const float4*)g_h2;
    bool inb    = d < N_NODES;
    bool active = inb && (q < 10);

    float d2 = 0.f; int p0 = 0, p1 = 0;
    if (inb) {
        float dv = g_dinv[d];
        d2 = dv * dv;
        p0 = g_rowptr[d]; p1 = g_rowptr[d + 1];
    }
    float4 acc = make_float4(0.f, 0.f, 0.f, 0.f);
    if (active) {
        float4 v  = h4[(size_t)d * 10 + q];
        float4 bb = ((const float4*)b2)[q];
        acc.x = v.x * d2 + bb.x; acc.y = v.y * d2 + bb.y;
        acc.z = v.z * d2 + bb.z; acc.w = v.w * d2 + bb.w;
    }
    int p = p0;
    for (; p + 1 < p1; p += 2) {
        int   s0 = g_csr_src[p],  s1 = g_csr_src[p + 1];
        float w0 = g_csr_w[p],    w1 = g_csr_w[p + 1];
        if (active) {
            float4 u0 = h4[(size_t)s0 * 10 + q];
            float4 u1 = h4[(size_t)s1 * 10 + q];
            acc.x += w0 * u0.x + w1 * u1.x;
            acc.y += w0 * u0.y + w1 * u1.y;
            acc.z += w0 * u0.z + w1 * u1.z;
            acc.w += w0 * u0.w + w1 * u1.w;
        }
    }
    if (p < p1) {
        int   s = g_csr_src[p];
        float w = g_csr_w[p];
        if (active) {
            float4 u = h4[(size_t)s * 10 + q];
            acc.x += w * u.x; acc.y += w * u.y;
            acc.z += w * u.z; acc.w += w * u.w;
        }
    }
    float m = active ? fmaxf(fmaxf(acc.x, acc.y), fmaxf(acc.z, acc.w)) : -FLT_MAX;
    #pragma unroll
    for (int o = 8; o; o >>= 1) m = fmaxf(m, __shfl_xor_sync(0xffffffffu, m, o, 16));
    float s = active ? (expf(acc.x - m) + expf(acc.y - m) +
                        expf(acc.z - m) + expf(acc.w - m)) : 0.f;
    #pragma unroll
    for (int o = 8; o; o >>= 1) s += __shfl_xor_sync(0xffffffffu, s, o, 16);
    float l = m + logf(s);
    if (active) {
        ((float4*)out)[(size_t)d * 10 + q] =
            make_float4(acc.x - l, acc.y - l, acc.z - l, acc.w - l);
    }
}

// ---------------- launch ------------------------------------------------------
extern "C" void kernel_launch(void* const* d_in, const int* in_sizes, int n_in,
                              void* d_out, int out_size) {
    const float* x    = (const float*)d_in[0];
    const void*  edge = d_in[1];
    const float* W1   = (const float*)d_in[2];
    const float* b1   = (const float*)d_in[3];
    const float* W2   = (const float*)d_in[4];
    const float* b2   = (const float*)d_in[5];
    float*       out  = (float*)d_out;

    cudaFuncSetAttribute(k_mlp, cudaFuncAttributeMaxDynamicSharedMemorySize, MLP_SMEM);

    k_pre      <<<(N_NODES + 255) / 256, 256>>>((const long long*)edge);
    k_edges    <<<(N_EDGES + 255) / 256, 256>>>(edge);
    k_scan1    <<<SCAN_B, 1024>>>();
    k_scan2    <<<1, 128>>>();
    k_scan3    <<<SCAN_B, 1024>>>();
    k_place    <<<(N_EDGES + 255) / 256, 256>>>();
    k_prep_w1  <<<(F_IN * F_HID + 255) / 256, 256>>>(W1);
    k_prep_w2  <<<(48 * F_HID + 255) / 256, 256>>>(W2);
    k_mlp      <<<(N_NODES + 63) / 64, 256, MLP_SMEM>>>(x, b1);
    k_layer2   <<<(N_NODES / 2 * 32 + 255) / 256, 256>>>(b2, out);
}

// round 10
// speedup vs baseline: 1.0910x; 1.0910x over previous
#include <cuda_runtime.h>
#include <cuda_bf16.h>
#include <mma.h>
#include <float.h>
#include <cstdint>
using namespace nvcuda;

#define N_NODES 100000
#define N_EDGES 1000000
#define F_IN    128
#define F_HID   256
#define F_OUT   40
#define SCAN_B  98

// ---------------- scratch ----------------------------------------------------
__device__ int   g_cnt   [N_NODES];
__device__ float g_dinv  [N_NODES];
__device__ int   g_srcA  [N_EDGES];
__device__ int   g_dstA  [N_EDGES];
__device__ int   g_rowptr[N_NODES + 1];
__device__ int   g_cursor[N_NODES];
__device__ int   g_csr_src[N_EDGES];
__device__ float g_csr_w  [N_EDGES];
__device__ int   g_bsum[SCAN_B];
__device__ int   g_boff[SCAN_B];
__device__ __align__(16) __nv_bfloat16 g_a1h[(size_t)N_NODES * F_IN];
__device__ __align__(16) __nv_bfloat16 g_a1l[(size_t)N_NODES * F_IN];
__device__ __align__(16) float g_h2 [(size_t)N_NODES * F_OUT];
__device__ __align__(16) __nv_bfloat16 g_w1h[128 * 256];   // [k][n] row-major
__device__ __align__(16) __nv_bfloat16 g_w1l[128 * 256];
__device__ __align__(16) __nv_bfloat16 g_w2h[256 * 48];    // [k][n48], n>=40 zero
__device__ __align__(16) __nv_bfloat16 g_w2l[256 * 48];
__device__ int   g_is32 = 0;   // sticky: dtype is fixed across replays

__device__ __forceinline__ void bsplit(float a, __nv_bfloat16& hi, __nv_bfloat16& lo) {
    hi = __float2bfloat16_rn(a);
    lo = __float2bfloat16_rn(a - __bfloat162float(hi));
}
__device__ __forceinline__ uint32_t pack_bf2(__nv_bfloat16 a, __nv_bfloat16 b) {
    __nv_bfloat162 t(a, b);
    return *(uint32_t*)&t;
}

// ---------------- fused: zero counts + dtype probe ----------------------------
__global__ void k_pre(const long long* __restrict__ e64) {
    int i = blockIdx.x * blockDim.x + threadIdx.x;
    if (i < N_NODES) g_cnt[i] = 0;
    if (blockIdx.x == 0) {
        for (int t = threadIdx.x; t < 8192; t += 256) {
            long long v = e64[(long long)t * 122];
            if (v < 0 || v >= N_NODES) g_is32 = 1;   // sticky across replays
        }
    }
}

__global__ void k_edges(const void* __restrict__ edge) {
    int e = blockIdx.x * blockDim.x + threadIdx.x;
    if (e >= N_EDGES) return;
    int s, d;
    if (g_is32) {
        const int* e32 = (const int*)edge;
        s = e32[e];  d = e32[N_EDGES + e];
    } else {
        const long long* e64 = (const long long*)edge;
        s = (int)e64[e];  d = (int)e64[N_EDGES + e];
    }
    g_srcA[e] = s;
    g_dstA[e] = d;
    atomicAdd(&g_cnt[d], 1);
}

// scan stage 1 (+ fused dinv)
__global__ __launch_bounds__(1024) void k_scan1() {
    __shared__ int wsum[32];
    int tid = threadIdx.x, lane = tid & 31, w = tid >> 5;
    int i = blockIdx.x * 1024 + tid;
    int v = 0;
    if (i < N_NODES) {
        v = g_cnt[i];
        g_dinv[i] = rsqrtf((float)(v + 1));
    }
    int r = v;
    #pragma unroll
    for (int o = 16; o; o >>= 1) r += __shfl_xor_sync(0xffffffffu, r, o);
    if (lane == 0) wsum[w] = r;
    __syncthreads();
    if (w == 0) {
        int y = wsum[lane];
        #pragma unroll
        for (int o = 16; o; o >>= 1) y += __shfl_xor_sync(0xffffffffu, y, o);
        if (lane == 0) g_bsum[blockIdx.x] = y;
    }
}

// parallel scan of the 98 block sums (1 block, 128 threads)
__global__ void k_scan2() {
    __shared__ int wsum[4];
    int tid = threadIdx.x, lane = tid & 31, w = tid >> 5;
    int v = (tid < SCAN_B) ? g_bsum[tid] : 0;
    int x = v;
    #pragma unroll
    for (int o = 1; o < 32; o <<= 1) {
        int y = __shfl_up_sync(0xffffffffu, x, o);
        if (lane >= o) x += y;
    }
    if (lane == 31) wsum[w] = x;
    __syncthreads();
    int base = 0;
    #pragma unroll
    for (int b = 0; b < 4; b++) base += (b < w) ? wsum[b] : 0;
    int incl = base + x;
    if (tid < SCAN_B) g_boff[tid] = incl - v;
    if (tid == SCAN_B - 1) g_rowptr[N_NODES] = incl;
}

__global__ __launch_bounds__(1024) void k_scan3() {
    __shared__ int wsum[32];
    int tid = threadIdx.x, lane = tid & 31, w = tid >> 5;
    int i = blockIdx.x * 1024 + tid;
    int v = (i < N_NODES) ? g_cnt[i] : 0;
    int x = v;
    #pragma unroll
    for (int o = 1; o < 32; o <<= 1) {
        int y = __shfl_up_sync(0xffffffffu, x, o);
        if (lane >= o) x += y;
    }
    if (lane == 31) wsum[w] = x;
    __syncthreads();
    if (w == 0) {
        int y = wsum[lane];
        #pragma unroll
        for (int o = 1; o < 32; o <<= 1) {
            int z = __shfl_up_sync(0xffffffffu, y, o);
            if (lane >= o) y += z;
        }
        wsum[lane] = y;
    }
    __syncthreads();
    if (i < N_NODES) {
        int off = g_boff[blockIdx.x] + x - v + (w > 0 ? wsum[w - 1] : 0);
        g_rowptr[i] = off;
        g_cursor[i] = off;
    }
}
__global__ void k_place() {
    int e = blockIdx.x * blockDim.x + threadIdx.x;
    if (e >= N_EDGES) return;
    int s = g_srcA[e], d = g_dstA[e];
    int pos = atomicAdd(&g_cursor[d], 1);
    g_csr_src[pos] = s;
    g_csr_w[pos]   = g_dinv[s] * g_dinv[d];
}

// ---------------- weight prep (merged): bf16 split ----------------------------
__global__ void k_prep_w(const float* __restrict__ W1, const float* __restrict__ W2) {
    int i = blockIdx.x * blockDim.x + threadIdx.x;
    if (i < F_IN * F_HID) {                       // W1: i = k*256 + n
        __nv_bfloat16 h, l;
        bsplit(W1[i], h, l);
        g_w1h[i] = h;
        g_w1l[i] = l;
    }
    int j = i - F_IN * F_HID;
    if (j >= 0 && j < 48 * F_HID) {               // W2: j = k*48 + n
        int k = j / 48, n = j - k * 48;
        float v = (n < F_OUT) ? W2[(size_t)k * F_OUT + n] : 0.f;
        __nv_bfloat16 h, l;
        bsplit(v, h, l);
        g_w2h[j] = h;
        g_w2l[j] = l;
    }
}

// ---------------- layer-1 aggregation (CSR, warp per dst) -> bf16 hi/lo ------
__global__ void k_agg1(const float* __restrict__ x) {
    int t    = blockIdx.x * blockDim.x + threadIdx.x;
    int d    = t >> 5;
    int lane = t & 31;
    if (d >= N_NODES) return;
    const float4* x4 = (const float4*)x;
    float dv = g_dinv[d];
    float d2 = dv * dv;
    float4 v = x4[(size_t)d * 32 + lane];
    float4 acc = make_float4(v.x * d2, v.y * d2, v.z * d2, v.w * d2);
    int p0 = g_rowptr[d], p1 = g_rowptr[d + 1];
    int p = p0;
    for (; p + 3 < p1; p += 4) {                 // 4-way MLP
        int   s0 = g_csr_src[p],     s1 = g_csr_src[p + 1];
        int   s2 = g_csr_src[p + 2], s3 = g_csr_src[p + 3];
        float w0 = g_csr_w[p],       w1 = g_csr_w[p + 1];
        float w2 = g_csr_w[p + 2],   w3 = g_csr_w[p + 3];
        float4 u0 = x4[(size_t)s0 * 32 + lane];
        float4 u1 = x4[(size_t)s1 * 32 + lane];
        float4 u2 = x4[(size_t)s2 * 32 + lane];
        float4 u3 = x4[(size_t)s3 * 32 + lane];
        acc.x += w0 * u0.x + w1 * u1.x + w2 * u2.x + w3 * u3.x;
        acc.y += w0 * u0.y + w1 * u1.y + w2 * u2.y + w3 * u3.y;
        acc.z += w0 * u0.z + w1 * u1.z + w2 * u2.z + w3 * u3.z;
        acc.w += w0 * u0.w + w1 * u1.w + w2 * u2.w + w3 * u3.w;
    }
    for (; p < p1; p++) {
        int   s = g_csr_src[p];
        float w = g_csr_w[p];
        float4 u = x4[(size_t)s * 32 + lane];
        acc.x += w * u.x; acc.y += w * u.y;
        acc.z += w * u.z; acc.w += w * u.w;
    }
    __nv_bfloat16 h0, l0, h1, l1, h2, l2, h3, l3;
    bsplit(acc.x, h0, l0); bsplit(acc.y, h1, l1);
    bsplit(acc.z, h2, l2); bsplit(acc.w, h3, l3);
    size_t base = (size_t)d * F_IN + lane * 4;
    *(uint32_t*)&g_a1h[base]     = pack_bf2(h0, h1);
    *(uint32_t*)&g_a1h[base + 2] = pack_bf2(h2, h3);
    *(uint32_t*)&g_a1l[base]     = pack_bf2(l0, l1);
    *(uint32_t*)&g_a1l[base + 2] = pack_bf2(l2, l3);
}

// ---------------- fused MLP: h2 = relu(agg1@W1+b1) @ W2 ----------------------
// 64 rows/block, 256 threads (8 warps). Split-bf16 (3 MMAs) both GEMMs.
// Smem aliasing for 2 CTAs/SM. Phase-A W1 staged 2 k-tiles per buffer:
//   buf0 = sm[SM_H +     0, +33792)   (k-tiles 2t)
//   buf1 = sm[SM_H + 33792, +33792)   (k-tiles 2t+1 prefetch)
// -> 4 __syncthreads in phase A instead of 8.
#define SM_H    0
#define SM_A    67584
#define MLP_SMEM 102400

// stage one (hi,lo) W1 k-tile pair into half-buffer `sub` of buffer `buf`
__device__ __forceinline__ void stage_b1(char* sm, int buf, int sub, int k, int tid) {
    __nv_bfloat16* Bh = (__nv_bfloat16*)(sm + SM_H + buf * 33792 + sub * 16896);
    __nv_bfloat16* Bl = (__nv_bfloat16*)(sm + SM_H + buf * 33792 + sub * 16896 + 8448);
    #pragma unroll
    for (int u = tid; u < 512; u += 256) {
        int r = u >> 5, c8 = (u & 31) << 3;
        *(uint4*)&Bh[r * 264 + c8] = *(const uint4*)&g_w1h[(k * 16 + r) * 256 + c8];
        *(uint4*)&Bl[r * 264 + c8] = *(const uint4*)&g_w1l[(k * 16 + r) * 256 + c8];
    }
}

__global__ __launch_bounds__(256, 2) void k_mlp(const float* __restrict__ b1) {
    extern __shared__ char sm[];
    __nv_bfloat16* Hh = (__nv_bfloat16*)(sm + SM_H);
    __nv_bfloat16* Hl = (__nv_bfloat16*)(sm + SM_H + 33792);
    __nv_bfloat16* Ah = (__nv_bfloat16*)(sm + SM_A);
    __nv_bfloat16* Al = (__nv_bfloat16*)(sm + SM_A + 17408);
    float*         stg = (float*)(sm + SM_A);      // aliases A (dead in epilogues)

    int tid = threadIdx.x, wid = tid >> 5, lane = tid & 31;
    int bm = blockIdx.x * 64;
    int rg = wid >> 1, cg = wid & 1;     // 4 row-groups x 2 col-groups

    // ---- load A (64 x 128) hi/lo ----
    for (int u = tid; u < 1024; u += 256) {
        int r = u >> 4, c8 = (u & 15) << 3;
        uint4 vh = make_uint4(0, 0, 0, 0), vl = make_uint4(0, 0, 0, 0);
        int gr = bm + r;
        if (gr < N_NODES) {
            vh = *(const uint4*)&g_a1h[(size_t)gr * F_IN + c8];
            vl = *(const uint4*)&g_a1l[(size_t)gr * F_IN + c8];
        }
        *(uint4*)&Ah[r * 136 + c8] = vh;
        *(uint4*)&Al[r * 136 + c8] = vl;
    }
    stage_b1(sm, 0, 0, 0, tid);
    stage_b1(sm, 0, 1, 1, tid);
    __syncthreads();

    // ---- phase A: H = relu(A @ W1 + b1), W1 double-buffered 2 k-tiles deep --
    wmma::fragment<wmma::accumulator, 16, 16, 16, float> acc[8];
    #pragma unroll
    for (int j = 0; j < 8; j++) wmma::fill_fragment(acc[j], 0.f);

    #pragma unroll
    for (int t2 = 0; t2 < 4; t2++) {              // pairs of k-steps
        int cur = t2 & 1;
        if (t2 < 3) {
            stage_b1(sm, 1 - cur, 0, 2 * t2 + 2, tid);
            stage_b1(sm, 1 - cur, 1, 2 * t2 + 3, tid);
        }
        #pragma unroll
        for (int kk = 0; kk < 2; kk++) {
            int k = 2 * t2 + kk;
            __nv_bfloat16* B1h = (__nv_bfloat16*)(sm + SM_H + cur * 33792 + kk * 16896);
            __nv_bfloat16* B1l = (__nv_bfloat16*)(sm + SM_H + cur * 33792 + kk * 16896 + 8448);

            wmma::fragment<wmma::matrix_a, 16, 16, 16, __nv_bfloat16, wmma::row_major> ah, al;
            wmma::load_matrix_sync(ah, &Ah[(rg * 16) * 136 + k * 16], 136);
            wmma::load_matrix_sync(al, &Al[(rg * 16) * 136 + k * 16], 136);
            #pragma unroll
            for (int j = 0; j < 8; j++) {
                wmma::fragment<wmma::matrix_b, 16, 16, 16, __nv_bfloat16, wmma::row_major> bh, bl;
                wmma::load_matrix_sync(bh, &B1h[cg * 128 + j * 16], 264);
                wmma::load_matrix_sync(bl, &B1l[cg * 128 + j * 16], 264);
                wmma::mma_sync(acc[j], ah, bh, acc[j]);
                wmma::mma_sync(acc[j], ah, bl, acc[j]);
                wmma::mma_sync(acc[j], al, bh, acc[j]);
            }
        }
        __syncthreads();
    }

    // ---- epilogue A: bias + relu + split -> H smem ----
    #pragma unroll
    for (int j = 0; j < 8; j++) {
        wmma::store_matrix_sync(&stg[wid * 256], acc[j], 16, wmma::mem_row_major);
        __syncwarp();
        int r  = lane >> 1, c0 = (lane & 1) * 8;
        int col = cg * 128 + j * 16 + c0;
        uint32_t hw[4], lw[4];
        #pragma unroll
        for (int e = 0; e < 8; e += 2) {
            float f0 = fmaxf(stg[wid * 256 + r * 16 + c0 + e]     + b1[col + e],     0.f);
            float f1 = fmaxf(stg[wid * 256 + r * 16 + c0 + e + 1] + b1[col + e + 1], 0.f);
            __nv_bfloat16 h0, l0, h1, l1;
            bsplit(f0, h0, l0); bsplit(f1, h1, l1);
            hw[e >> 1] = pack_bf2(h0, h1);
            lw[e >> 1] = pack_bf2(l0, l1);
        }
        int row = rg * 16 + r;
        *(uint4*)&Hh[row * 264 + col] = *(uint4*)hw;
        *(uint4*)&Hl[row * 264 + col] = *(uint4*)lw;
        __syncwarp();
    }
    __syncthreads();

    // ---- phase B: H2 = H @ W2 (N padded to 48: cg0 -> 2 tiles, cg1 -> 1) ----
    int nTiles = (cg == 0) ? 2 : 1;
    wmma::fragment<wmma::accumulator, 16, 16, 16, float> acc2[2];
    #pragma unroll
    for (int j = 0; j < 2; j++) wmma::fill_fragment(acc2[j], 0.f);

    #pragma unroll
    for (int k = 0; k < 16; k++) {
        wmma::fragment<wmma::matrix_a, 16, 16, 16, __nv_bfloat16, wmma::row_major> ah, al;
        wmma::load_matrix_sync(ah, &Hh[(rg * 16) * 264 + k * 16], 264);
        wmma::load_matrix_sync(al, &Hl[(rg * 16) * 264 + k * 16], 264);
        for (int j = 0; j < nTiles; j++) {
            int nc = (cg == 0) ? j * 16 : 32;
            wmma::fragment<wmma::matrix_b, 16, 16, 16, __nv_bfloat16, wmma::row_major> bh, bl;
            wmma::load_matrix_sync(bh, &g_w2h[(k * 16) * 48 + nc], 48);
            wmma::load_matrix_sync(bl, &g_w2l[(k * 16) * 48 + nc], 48);
            wmma::mma_sync(acc2[j], ah, bh, acc2[j]);
            wmma::mma_sync(acc2[j], ah, bl, acc2[j]);
            wmma::mma_sync(acc2[j], al, bh, acc2[j]);
        }
    }

    // ---- epilogue B: write h2 (cols < 40) ----
    for (int j = 0; j < nTiles; j++) {
        int ncb = (cg == 0) ? j * 16 : 32;
        wmma::store_matrix_sync(&stg[wid * 256], acc2[j], 16, wmma::mem_row_major);
        __syncwarp();
        int r  = lane >> 1, c0 = (lane & 1) * 8;
        int row = bm + rg * 16 + r;
        int col = ncb + c0;
        if (row < N_NODES && col < F_OUT) {
            float* dst = g_h2 + (size_t)row * F_OUT + col;
            *(float4*)(dst)     = *(float4*)&stg[wid * 256 + r * 16 + c0];
            *(float4*)(dst + 4) = *(float4*)&stg[wid * 256 + r * 16 + c0 + 4];
        }
        __syncwarp();
    }
}

// ---------------- layer-2 aggregation + bias + log_softmax (fused) -----------
// 2 dst per warp (16-lane halves); lanes q<10 own one float4 each.
__global__ void k_layer2(const float* __restrict__ b2, float* __restrict__ out) {
    int t    = blockIdx.x * blockDim.x + threadIdx.x;
    int warp = t >> 5;
    int lane = t & 31;
    int half = lane >> 4;
    int q    = lane & 15;
    int d    = warp * 2 + half;
    const float4* h4 = (const float4*)g_h2;
    bool inb    = d < N_NODES;
    bool active = inb && (q < 10);

    float d2 = 0.f; int p0 = 0, p1 = 0;
    if (inb) {
        float dv = g_dinv[d];
        d2 = dv * dv;
        p0 = g_rowptr[d]; p1 = g_rowptr[d + 1];
    }
    float4 acc = make_float4(0.f, 0.f, 0.f, 0.f);
    if (active) {
        float4 v  = h4[(size_t)d * 10 + q];
        float4 bb = ((const float4*)b2)[q];
        acc.x = v.x * d2 + bb.x; acc.y = v.y * d2 + bb.y;
        acc.z = v.z * d2 + bb.z; acc.w = v.w * d2 + bb.w;
    }
    int p = p0;
    for (; p + 1 < p1; p += 2) {
        int   s0 = g_csr_src[p],  s1 = g_csr_src[p + 1];
        float w0 = g_csr_w[p],    w1 = g_csr_w[p + 1];
        if (active) {
            float4 u0 = h4[(size_t)s0 * 10 + q];
            float4 u1 = h4[(size_t)s1 * 10 + q];
            acc.x += w0 * u0.x + w1 * u1.x;
            acc.y += w0 * u0.y + w1 * u1.y;
            acc.z += w0 * u0.z + w1 * u1.z;
            acc.w += w0 * u0.w + w1 * u1.w;
        }
    }
    if (p < p1) {
        int   s = g_csr_src[p];
        float w = g_csr_w[p];
        if (active) {
            float4 u = h4[(size_t)s * 10 + q];
            acc.x += w * u.x; acc.y += w * u.y;
            acc.z += w * u.z; acc.w += w * u.w;
        }
    }
    float m = active ? fmaxf(fmaxf(acc.x, acc.y), fmaxf(acc.z, acc.w)) : -FLT_MAX;
    #pragma unroll
    for (int o = 8; o; o >>= 1) m = fmaxf(m, __shfl_xor_sync(0xffffffffu, m, o, 16));
    float s = active ? (expf(acc.x - m) + expf(acc.y - m) +
                        expf(acc.z - m) + expf(acc.w - m)) : 0.f;
    #pragma unroll
    for (int o = 8; o; o >>= 1) s += __shfl_xor_sync(0xffffffffu, s, o, 16);
    float l = m + logf(s);
    if (active) {
        ((float4*)out)[(size_t)d * 10 + q] =
            make_float4(acc.x - l, acc.y - l, acc.z - l, acc.w - l);
    }
}

// ---------------- launch ------------------------------------------------------
extern "C" void kernel_launch(void* const* d_in, const int* in_sizes, int n_in,
                              void* d_out, int out_size) {
    const float* x    = (const float*)d_in[0];
    const void*  edge = d_in[1];
    const float* W1   = (const float*)d_in[2];
    const float* b1   = (const float*)d_in[3];
    const float* W2   = (const float*)d_in[4];
    const float* b2   = (const float*)d_in[5];
    float*       out  = (float*)d_out;

    cudaFuncSetAttribute(k_mlp, cudaFuncAttributeMaxDynamicSharedMemorySize, MLP_SMEM);

    k_pre      <<<(N_NODES + 255) / 256, 256>>>((const long long*)edge);
    k_edges    <<<(N_EDGES + 255) / 256, 256>>>(edge);
    k_scan1    <<<SCAN_B, 1024>>>();
    k_scan2    <<<1, 128>>>();
    k_scan3    <<<SCAN_B, 1024>>>();
    k_place    <<<(N_EDGES + 255) / 256, 256>>>();
    k_prep_w   <<<(F_IN * F_HID + 48 * F_HID + 255) / 256, 256>>>(W1, W2);
    k_agg1     <<<(N_NODES * 32 + 255) / 256, 256>>>(x);
    k_mlp      <<<(N_NODES + 63) / 64, 256, MLP_SMEM>>>(b1);
    k_layer2   <<<(N_NODES / 2 * 32 + 255) / 256, 256>>>(b2, out);
}